// round 14
// baseline (speedup 1.0000x reference)
#include <cuda_runtime.h>
#include <cuda_bf16.h>
#include <stdint.h>
#include <math.h>

#define HEADS 12
#define HEAD_SIZE 64
#define HIDDEN 768
#define EPROJ 1536
#define SEQ 1024
#define NB 8
#define NEGV 1000000000000.0f

// staging buffers
__device__ __align__(128) uint8_t g_x8[NB * SEQ * HIDDEN];          // x e4m3, scale 1
__device__ __align__(128) uint8_t g_w8[EPROJ * HIDDEN];             // W^T e4m3 *64, rows permuted
__device__ __align__(128) __nv_bfloat16 g_q[NB * HEADS * SEQ * HEAD_SIZE];
__device__ __align__(128) __nv_bfloat16 g_k[NB * HEADS * SEQ * HEAD_SIZE]; // rows permuted
__device__ __align__(128) float2 g_rope[SEQ * 32];                  // [n][freq] = (cos, sin)

#define SWZ(o) ((o) ^ (((o) >> 3) & 0x70))

// Involutive permutation within 32-row groups: c = (a<<3)|(b<<1)|q -> (b<<3)|(a<<1)|q.
__device__ __forceinline__ int permg(int c) {
    return (((c & 7) >> 1) << 3) + ((c >> 3) << 1) + (c & 1);
}

__device__ __forceinline__ uint32_t smem_u32(const void* p) {
    uint32_t a;
    asm("{ .reg .u64 t; cvta.to.shared.u64 t, %1; cvt.u32.u64 %0, t; }"
        : "=r"(a) : "l"(p));
    return a;
}

__device__ __forceinline__ void ldmx4(uint32_t* r, uint32_t addr) {
    asm volatile("ldmatrix.sync.aligned.m8n8.x4.shared.b16 {%0,%1,%2,%3}, [%4];"
                 : "=r"(r[0]), "=r"(r[1]), "=r"(r[2]), "=r"(r[3]) : "r"(addr));
}
__device__ __forceinline__ void ldmx2(uint32_t* r, uint32_t addr) {
    asm volatile("ldmatrix.sync.aligned.m8n8.x2.shared.b16 {%0,%1}, [%2];"
                 : "=r"(r[0]), "=r"(r[1]) : "r"(addr));
}
__device__ __forceinline__ void mma16816(float* c, const uint32_t* a,
                                         const uint32_t* b) {
    asm volatile(
        "mma.sync.aligned.m16n8k16.row.col.f32.bf16.bf16.f32 "
        "{%0,%1,%2,%3}, {%4,%5,%6,%7}, {%8,%9}, {%0,%1,%2,%3};"
        : "+f"(c[0]), "+f"(c[1]), "+f"(c[2]), "+f"(c[3])
        : "r"(a[0]), "r"(a[1]), "r"(a[2]), "r"(a[3]), "r"(b[0]), "r"(b[1]));
}
// fp8 e4m3 mma, K=32, fp32 accum
__device__ __forceinline__ void mma8(float* c, const uint32_t* a,
                                     const uint32_t* b) {
    asm volatile(
        "mma.sync.aligned.m16n8k32.row.col.f32.e4m3.e4m3.f32 "
        "{%0,%1,%2,%3}, {%4,%5,%6,%7}, {%8,%9}, {%0,%1,%2,%3};"
        : "+f"(c[0]), "+f"(c[1]), "+f"(c[2]), "+f"(c[3])
        : "r"(a[0]), "r"(a[1]), "r"(a[2]), "r"(a[3]), "r"(b[0]), "r"(b[1]));
}

__device__ __forceinline__ uint16_t pack2_e4m3(float lo, float hi) {
    uint16_t r;
    asm("cvt.rn.satfinite.e4m3x2.f32 %0, %1, %2;" : "=h"(r) : "f"(hi), "f"(lo));
    return r;
}
__device__ __forceinline__ uint32_t pack4_e4m3(float a0, float a1, float a2,
                                               float a3) {
    uint16_t lo = pack2_e4m3(a0, a1);
    uint16_t hi = pack2_e4m3(a2, a3);
    return (uint32_t)lo | ((uint32_t)hi << 16);
}

// 256-bit streaming store (Blackwell): 32 lanes x 32B = 8 full 128B lines.
__device__ __forceinline__ void stg256_cs(float* p, const float* v) {
    asm volatile(
        "st.global.cs.v8.f32 [%0], {%1,%2,%3,%4,%5,%6,%7,%8};"
        :: "l"(p), "f"(v[0]), "f"(v[1]), "f"(v[2]), "f"(v[3]),
           "f"(v[4]), "f"(v[5]), "f"(v[6]), "f"(v[7])
        : "memory");
}

// ---------------------------------------------------------------------------
// conversion / table kernels
// ---------------------------------------------------------------------------
__global__ void rope_table_kernel() {
    const int i = blockIdx.x * blockDim.x + threadIdx.x;  // n*32 + freq
    const int n = i >> 5;
    const int f = i & 31;
    const float inv = exp2f(-(float)(2 * f) * (13.287712379549449f / 64.0f));
    float s, c;
    sincosf((float)n * inv, &s, &c);
    g_rope[i] = make_float2(c, s);
}

__global__ void conv_x_kernel(const float* __restrict__ x) {
    int i = blockIdx.x * blockDim.x + threadIdx.x;  // 8 floats per thread
    float4 v0 = ((const float4*)x)[i * 2];
    float4 v1 = ((const float4*)x)[i * 2 + 1];
    uint2 u;
    u.x = pack4_e4m3(v0.x, v0.y, v0.z, v0.w);
    u.y = pack4_e4m3(v1.x, v1.y, v1.z, v1.w);
    ((uint2*)g_x8)[i] = u;
}

// W^T e4m3 (*64), rows permuted within aligned 32-groups.
__global__ void conv_wt_kernel(const float* __restrict__ W) {
    __shared__ float t[32][33];
    const int bx = blockIdx.x * 32, by = blockIdx.y * 32;
    const int tx = threadIdx.x, ty = threadIdx.y;
#pragma unroll
    for (int j = 0; j < 4; j++)
        t[ty + j * 8][tx] = W[(size_t)(by + ty + j * 8) * EPROJ + bx + tx];
    __syncthreads();
    const int r2 = ty + (tx >> 3) * 8;
    const int c4 = (tx & 7) * 4;
    uint32_t p = pack4_e4m3(t[c4 + 0][r2] * 64.f, t[c4 + 1][r2] * 64.f,
                            t[c4 + 2][r2] * 64.f, t[c4 + 3][r2] * 64.f);
    *(uint32_t*)(g_w8 + (size_t)(bx + permg(r2)) * HIDDEN + by + c4) = p;
}

// ---------------------------------------------------------------------------
// Kernel 1: proj = x @ W (+bias) then RoPE -> g_q / g_k (bf16)
// FP8 e4m3 mma m16n8k32, CTA tile 128x128, K in 6 chunks of 128.
// RoPE trig from the precomputed L2-resident table (no sincosf in epilogue).
// ---------------------------------------------------------------------------
__global__ void __launch_bounds__(256, 2) proj_kernel(const float* __restrict__ bias) {
    __shared__ __align__(128) uint8_t sA[128 * 128];  // 16KB
    __shared__ __align__(128) uint8_t sB[128 * 128];  // 16KB
    __shared__ float s_bias[128];

    const int tid = threadIdx.x;
    const int lane = tid & 31;
    const int wid = tid >> 5;
    const int wm = wid & 1;
    const int wn = wid >> 1;
    const int h = blockIdx.x;
    const int rowBase = blockIdx.y * 128;
    const int colBase = h * 128;

    if (tid < 128) s_bias[tid] = bias[colBase + tid];

    const uint32_t sAb = smem_u32(sA);
    const uint32_t sBb = smem_u32(sB);

    float acc[4][4][4] = {};

    for (int ch = 0; ch < 6; ch++) {
        const int k0 = ch * 128;
        __syncthreads();
#pragma unroll
        for (int i = 0; i < 4; i++) {
            int e = tid + i * 256;   // 1024 uint4 per tile
            int r = e >> 3;
            int c = e & 7;
            uint32_t so = SWZ((uint32_t)(r * 128 + c * 16));
            *(uint4*)(sA + so) =
                *(const uint4*)(g_x8 + (size_t)(rowBase + r) * HIDDEN + k0 + c * 16);
            *(uint4*)(sB + so) =
                *(const uint4*)(g_w8 + (size_t)(colBase + r) * HIDDEN + k0 + c * 16);
        }
        __syncthreads();

#pragma unroll
        for (int ks = 0; ks < 4; ks++) {   // 4 x K=32 per 128B chunk
            uint32_t aF[4][4], bF[4][2];
#pragma unroll
            for (int mi = 0; mi < 4; mi++) {
                int r = wm * 64 + mi * 16 + (lane & 15);
                int cc = ks * 2 + (lane >> 4);
                ldmx4(aF[mi], sAb + SWZ((uint32_t)(r * 128 + cc * 16)));
            }
#pragma unroll
            for (int ni = 0; ni < 4; ni++) {
                int l = lane & 15;
                int r = wn * 32 + ni * 8 + (l & 7);
                int cc = ks * 2 + (l >> 3);
                ldmx2(bF[ni], sBb + SWZ((uint32_t)(r * 128 + cc * 16)));
            }
#pragma unroll
            for (int mi = 0; mi < 4; mi++)
#pragma unroll
                for (int ni = 0; ni < 4; ni++)
                    mma8(acc[mi][ni], aF[mi], bF[ni]);
        }
    }

    // Epilogue: lane owns cols bc..bc+7; unscale 1/64, +bias, RoPE (table),
    // bf16, one 16B store per (mi, rr). k rows stored permuted.
    const int bc = wn * 32 + (lane & 3) * 8;
    const int half = (bc >> 6) & 1;
    const int d0 = bc & 63;
    __nv_bfloat16* dstBase = half ? g_k : g_q;
#pragma unroll
    for (int mi = 0; mi < 4; mi++) {
#pragma unroll
        for (int rr = 0; rr < 2; rr++) {
            const int r = rowBase + wm * 64 + mi * 16 + (lane >> 2) + rr * 8;
            const int bb = r >> 10;
            const int n = r & (SEQ - 1);
            const int nw = half ? ((n & ~31) | permg(n & 31)) : n;
            const float2* rp = g_rope + n * 32 + (d0 >> 1);
            __nv_bfloat16* drow =
                dstBase + ((size_t)(bb * HEADS + h) * SEQ + nw) * HEAD_SIZE;
            uint32_t pk[4];
#pragma unroll
            for (int j = 0; j < 4; j++) {
                const float2 cs2 = __ldg(rp + j);
                const float v0 = acc[mi][j][rr * 2 + 0] * 0.015625f + s_bias[bc + 2 * j];
                const float v1 = acc[mi][j][rr * 2 + 1] * 0.015625f + s_bias[bc + 2 * j + 1];
                __nv_bfloat162 o;
                o.x = __float2bfloat16(v0 * cs2.x - v1 * cs2.y);
                o.y = __float2bfloat16(v1 * cs2.x + v0 * cs2.y);
                pk[j] = *(uint32_t*)&o;
            }
            uint4 u;
            u.x = pk[0]; u.y = pk[1]; u.z = pk[2]; u.w = pk[3];
            *(uint4*)(drow + d0) = u;
        }
    }
}

// ---------------------------------------------------------------------------
// Kernel 2: logits tile 128(m) x 64(n) per CTA, 3 CTAs/SM (unchanged R12/13).
// ---------------------------------------------------------------------------
__global__ void __launch_bounds__(256, 3) logits_kernel(const float* __restrict__ mask,
                                                        float* __restrict__ out) {
    __shared__ __align__(128) __nv_bfloat16 sQ[128 * 64];  // 16KB
    __shared__ __align__(128) __nv_bfloat16 sK[64 * 64];   // 8KB
    __shared__ float s_mk[64];

    const int tid = threadIdx.x;
    const int lane = tid & 31;
    const int wid = tid >> 5;
    const int wm = wid & 3;    // 0..3 (m)
    const int wn = wid >> 2;   // 0..1 (n)
    const int z = blockIdx.z;
    const int b = z / HEADS;
    const int m0 = blockIdx.y << 7;
    const int n0 = blockIdx.x << 6;

    if (tid < 64) s_mk[tid] = mask[(size_t)b * SEQ + n0 + tid];

    float acc[2][4][4] = {};

    const bool skip = (m0 >= n0 + 64);   // tile strictly below diagonal
    if (!skip) {
        const __nv_bfloat16* qsrc = g_q + ((size_t)z * SEQ + m0) * HEAD_SIZE;
        const __nv_bfloat16* ksrc = g_k + ((size_t)z * SEQ + n0) * HEAD_SIZE;

#pragma unroll
        for (int i = 0; i < 4; i++) {     // 1024 uint4 for Q
            int e = tid + i * 256;
            uint32_t so = SWZ((uint32_t)(e * 16));
            *(uint4*)((char*)sQ + so) = ((const uint4*)qsrc)[e];
        }
#pragma unroll
        for (int i = 0; i < 2; i++) {     // 512 uint4 for K
            int e = tid + i * 256;
            uint32_t so = SWZ((uint32_t)(e * 16));
            *(uint4*)((char*)sK + so) = ((const uint4*)ksrc)[e];
        }
        __syncthreads();

        const uint32_t sQb = smem_u32(sQ);
        const uint32_t sKb = smem_u32(sK);

#pragma unroll
        for (int ks = 0; ks < 4; ks++) {
            uint32_t aF[2][4], bF[4][2];
#pragma unroll
            for (int mi = 0; mi < 2; mi++) {
                int r = wm * 32 + mi * 16 + (lane & 15);
                int cc = ks * 2 + (lane >> 4);
                ldmx4(aF[mi], sQb + SWZ((uint32_t)(r * 128 + cc * 16)));
            }
#pragma unroll
            for (int ni = 0; ni < 4; ni++) {
                int l = lane & 15;
                int r = wn * 32 + ni * 8 + (l & 7);
                int cc = ks * 2 + (l >> 3);
                ldmx2(bF[ni], sKb + SWZ((uint32_t)(r * 128 + cc * 16)));
            }
#pragma unroll
            for (int mi = 0; mi < 2; mi++)
#pragma unroll
                for (int ni = 0; ni < 4; ni++)
                    mma16816(acc[mi][ni], aF[mi], bF[ni]);
        }
    } else {
        __syncthreads();
    }

    // Epilogue: lane owns cols bc..bc+7; folded mask/causal/scale; STG.256.cs.
    const int bc = wn * 32 + (lane & 3) * 8;
    float s_j[8], o_j[8];
#pragma unroll
    for (int j = 0; j < 8; j++) {
        const float mk = s_mk[bc + j];
        s_j[j] = mk * 0.125f;
        o_j[j] = (NEGV * 0.125f) * (mk - 1.0f);
    }
#pragma unroll
    for (int mi = 0; mi < 2; mi++) {
#pragma unroll
        for (int rr = 0; rr < 2; rr++) {
            const int m = m0 + wm * 32 + mi * 16 + (lane >> 2) + rr * 8;
            const float mq = mask[(size_t)b * SEQ + m];
            const float rbias = NEGV * (mq - 1.0f);
            float* orow = out + ((size_t)z * SEQ + m) * SEQ + n0;
            float v[8];
#pragma unroll
            for (int j = 0; j < 4; j++) {
#pragma unroll
                for (int q = 0; q < 2; q++) {
                    const int jj = 2 * j + q;
                    const float t = fmaf(acc[mi][j][rr * 2 + q], mq, rbias);
                    float r = fmaf(t, s_j[jj], o_j[jj]);
                    if (m > n0 + bc + jj) r -= (NEGV * 0.125f);
                    v[jj] = r;
                }
            }
            stg256_cs(orow + bc, v);
        }
    }
}

// ---------------------------------------------------------------------------
extern "C" void kernel_launch(void* const* d_in, const int* in_sizes, int n_in,
                              void* d_out, int out_size) {
    const float* x = (const float*)d_in[0];
    const float* W = (const float*)d_in[1];
    const float* bias = (const float*)d_in[2];
    const float* mask = (const float*)d_in[3];
    float* out = (float*)d_out;

    rope_table_kernel<<<(SEQ * 32) / 256, 256>>>();
    conv_x_kernel<<<(NB * SEQ * HIDDEN / 8) / 256, 256>>>(x);
    conv_wt_kernel<<<dim3(EPROJ / 32, HIDDEN / 32), dim3(32, 8)>>>(W);

    proj_kernel<<<dim3(EPROJ / 128, NB * SEQ / 128), 256>>>(bias);

    logits_kernel<<<dim3(SEQ / 64, SEQ / 128, NB * HEADS), 256>>>(mask, out);
}

// round 15
// speedup vs baseline: 1.0486x; 1.0486x over previous
#include <cuda_runtime.h>
#include <cuda_bf16.h>
#include <stdint.h>
#include <math.h>

#define HEADS 12
#define HEAD_SIZE 64
#define HIDDEN 768
#define EPROJ 1536
#define SEQ 1024
#define NB 8
#define NEGV 1000000000000.0f

// staging buffers
__device__ __align__(128) uint8_t g_x8[NB * SEQ * HIDDEN];          // x e4m3, scale 1
__device__ __align__(128) uint8_t g_w8[EPROJ * HIDDEN];             // W^T e4m3 *64, rows permuted
__device__ __align__(128) __nv_bfloat16 g_q[NB * HEADS * SEQ * HEAD_SIZE];
__device__ __align__(128) __nv_bfloat16 g_k[NB * HEADS * SEQ * HEAD_SIZE]; // rows permuted
__device__ __align__(128) float2 g_rope[SEQ * 32];                  // [n][freq] = (cos, sin)

#define SWZ(o) ((o) ^ (((o) >> 3) & 0x70))

// Involutive permutation within 32-row groups.
__device__ __forceinline__ int permg(int c) {
    return (((c & 7) >> 1) << 3) + ((c >> 3) << 1) + (c & 1);
}

__device__ __forceinline__ uint32_t smem_u32(const void* p) {
    uint32_t a;
    asm("{ .reg .u64 t; cvta.to.shared.u64 t, %1; cvt.u32.u64 %0, t; }"
        : "=r"(a) : "l"(p));
    return a;
}

__device__ __forceinline__ void ldmx4(uint32_t* r, uint32_t addr) {
    asm volatile("ldmatrix.sync.aligned.m8n8.x4.shared.b16 {%0,%1,%2,%3}, [%4];"
                 : "=r"(r[0]), "=r"(r[1]), "=r"(r[2]), "=r"(r[3]) : "r"(addr));
}
__device__ __forceinline__ void ldmx2(uint32_t* r, uint32_t addr) {
    asm volatile("ldmatrix.sync.aligned.m8n8.x2.shared.b16 {%0,%1}, [%2];"
                 : "=r"(r[0]), "=r"(r[1]) : "r"(addr));
}
__device__ __forceinline__ void mma16816(float* c, const uint32_t* a,
                                         const uint32_t* b) {
    asm volatile(
        "mma.sync.aligned.m16n8k16.row.col.f32.bf16.bf16.f32 "
        "{%0,%1,%2,%3}, {%4,%5,%6,%7}, {%8,%9}, {%0,%1,%2,%3};"
        : "+f"(c[0]), "+f"(c[1]), "+f"(c[2]), "+f"(c[3])
        : "r"(a[0]), "r"(a[1]), "r"(a[2]), "r"(a[3]), "r"(b[0]), "r"(b[1]));
}
// fp8 e4m3 mma, K=32, fp32 accum
__device__ __forceinline__ void mma8(float* c, const uint32_t* a,
                                     const uint32_t* b) {
    asm volatile(
        "mma.sync.aligned.m16n8k32.row.col.f32.e4m3.e4m3.f32 "
        "{%0,%1,%2,%3}, {%4,%5,%6,%7}, {%8,%9}, {%0,%1,%2,%3};"
        : "+f"(c[0]), "+f"(c[1]), "+f"(c[2]), "+f"(c[3])
        : "r"(a[0]), "r"(a[1]), "r"(a[2]), "r"(a[3]), "r"(b[0]), "r"(b[1]));
}

__device__ __forceinline__ uint16_t pack2_e4m3(float lo, float hi) {
    uint16_t r;
    asm("cvt.rn.satfinite.e4m3x2.f32 %0, %1, %2;" : "=h"(r) : "f"(hi), "f"(lo));
    return r;
}
__device__ __forceinline__ uint32_t pack4_e4m3(float a0, float a1, float a2,
                                               float a3) {
    uint16_t lo = pack2_e4m3(a0, a1);
    uint16_t hi = pack2_e4m3(a2, a3);
    return (uint32_t)lo | ((uint32_t)hi << 16);
}

// 256-bit streaming store (Blackwell): 32 lanes x 32B = 8 full 128B lines.
__device__ __forceinline__ void stg256_cs(float* p, const float* v) {
    asm volatile(
        "st.global.cs.v8.f32 [%0], {%1,%2,%3,%4,%5,%6,%7,%8};"
        :: "l"(p), "f"(v[0]), "f"(v[1]), "f"(v[2]), "f"(v[3]),
           "f"(v[4]), "f"(v[5]), "f"(v[6]), "f"(v[7])
        : "memory");
}

#define CP_ASYNC16(dst, src) \
    asm volatile("cp.async.cg.shared.global [%0], [%1], 16;" \
                 :: "r"(dst), "l"(src) : "memory")
#define CP_COMMIT asm volatile("cp.async.commit_group;" ::: "memory")
#define CP_WAIT0 asm volatile("cp.async.wait_group 0;" ::: "memory")

// ---------------------------------------------------------------------------
// conversion / table kernels
// ---------------------------------------------------------------------------
__global__ void rope_table_kernel() {
    const int i = blockIdx.x * blockDim.x + threadIdx.x;  // n*32 + freq
    const int n = i >> 5;
    const int f = i & 31;
    const float inv = exp2f(-(float)(2 * f) * (13.287712379549449f / 64.0f));
    float s, c;
    sincosf((float)n * inv, &s, &c);
    g_rope[i] = make_float2(c, s);
}

__global__ void conv_x_kernel(const float* __restrict__ x) {
    int i = blockIdx.x * blockDim.x + threadIdx.x;  // 8 floats per thread
    float4 v0 = ((const float4*)x)[i * 2];
    float4 v1 = ((const float4*)x)[i * 2 + 1];
    uint2 u;
    u.x = pack4_e4m3(v0.x, v0.y, v0.z, v0.w);
    u.y = pack4_e4m3(v1.x, v1.y, v1.z, v1.w);
    ((uint2*)g_x8)[i] = u;
}

// W^T e4m3 (*64), rows permuted within aligned 32-groups.
__global__ void conv_wt_kernel(const float* __restrict__ W) {
    __shared__ float t[32][33];
    const int bx = blockIdx.x * 32, by = blockIdx.y * 32;
    const int tx = threadIdx.x, ty = threadIdx.y;
#pragma unroll
    for (int j = 0; j < 4; j++)
        t[ty + j * 8][tx] = W[(size_t)(by + ty + j * 8) * EPROJ + bx + tx];
    __syncthreads();
    const int r2 = ty + (tx >> 3) * 8;
    const int c4 = (tx & 7) * 4;
    uint32_t p = pack4_e4m3(t[c4 + 0][r2] * 64.f, t[c4 + 1][r2] * 64.f,
                            t[c4 + 2][r2] * 64.f, t[c4 + 3][r2] * 64.f);
    *(uint32_t*)(g_w8 + (size_t)(bx + permg(r2)) * HIDDEN + by + c4) = p;
}

// ---------------------------------------------------------------------------
// Kernel 1: proj = x @ W (+bias) then RoPE -> g_q / g_k (bf16)
// FP8 e4m3 mma, CTA tile 128x128, K in 6 chunks of 128, cp.async 2-stage
// pipeline: chunk ch+1 transfers while chunk ch runs mma.
// Dynamic smem: stage s at s*32768 (A 16KB + B 16KB), bias at 65536.
// ---------------------------------------------------------------------------
#define PROJ_SMEM (65536 + 512)

__global__ void __launch_bounds__(256, 2) proj_kernel(const float* __restrict__ bias) {
    extern __shared__ __align__(128) uint8_t dsm[];
    float* s_bias = (float*)(dsm + 65536);

    const int tid = threadIdx.x;
    const int lane = tid & 31;
    const int wid = tid >> 5;
    const int wm = wid & 1;
    const int wn = wid >> 1;
    const int h = blockIdx.x;
    const int rowBase = blockIdx.y * 128;
    const int colBase = h * 128;

    if (tid < 128) s_bias[tid] = bias[colBase + tid];

    const uint32_t sbase = smem_u32(dsm);

    // Per-thread load slots: 4 uint4 per tile.
    int lr[4], lc[4];
    uint32_t lso[4];
#pragma unroll
    for (int i = 0; i < 4; i++) {
        int e = tid + i * 256;
        lr[i] = e >> 3;
        lc[i] = (e & 7) * 16;
        lso[i] = SWZ((uint32_t)(lr[i] * 128 + (e & 7) * 16));
    }

#define PROJ_ISSUE(ch)                                                        \
    {                                                                         \
        const int k0_ = (ch) * 128;                                           \
        const uint32_t sb_ = sbase + ((ch) & 1) * 32768;                      \
        _Pragma("unroll") for (int i = 0; i < 4; i++) {                       \
            CP_ASYNC16(sb_ + lso[i],                                          \
                       g_x8 + (size_t)(rowBase + lr[i]) * HIDDEN + k0_ + lc[i]); \
            CP_ASYNC16(sb_ + 16384 + lso[i],                                  \
                       g_w8 + (size_t)(colBase + lr[i]) * HIDDEN + k0_ + lc[i]); \
        }                                                                     \
        CP_COMMIT;                                                            \
    }

    float acc[4][4][4] = {};

    PROJ_ISSUE(0);
    for (int ch = 0; ch < 6; ch++) {
        CP_WAIT0;            // stage ch data complete (only group ch outstanding)
        __syncthreads();     // all warps done with mma(ch-1) -> stage reuse safe
        if (ch < 5) PROJ_ISSUE(ch + 1);   // overlaps with mma below

        const uint32_t sAb = sbase + (ch & 1) * 32768;
        const uint32_t sBb = sAb + 16384;
#pragma unroll
        for (int ks = 0; ks < 4; ks++) {   // 4 x K=32 per 128B chunk
            uint32_t aF[4][4], bF[4][2];
#pragma unroll
            for (int mi = 0; mi < 4; mi++) {
                int r = wm * 64 + mi * 16 + (lane & 15);
                int cc = ks * 2 + (lane >> 4);
                ldmx4(aF[mi], sAb + SWZ((uint32_t)(r * 128 + cc * 16)));
            }
#pragma unroll
            for (int ni = 0; ni < 4; ni++) {
                int l = lane & 15;
                int r = wn * 32 + ni * 8 + (l & 7);
                int cc = ks * 2 + (l >> 3);
                ldmx2(bF[ni], sBb + SWZ((uint32_t)(r * 128 + cc * 16)));
            }
#pragma unroll
            for (int mi = 0; mi < 4; mi++)
#pragma unroll
                for (int ni = 0; ni < 4; ni++)
                    mma8(acc[mi][ni], aF[mi], bF[ni]);
        }
    }

    // Epilogue: lane owns cols bc..bc+7; unscale 1/64, +bias, RoPE (table),
    // bf16, one 16B store per (mi, rr). k rows stored permuted.
    const int bc = wn * 32 + (lane & 3) * 8;
    const int half = (bc >> 6) & 1;
    const int d0 = bc & 63;
    __nv_bfloat16* dstBase = half ? g_k : g_q;
#pragma unroll
    for (int mi = 0; mi < 4; mi++) {
#pragma unroll
        for (int rr = 0; rr < 2; rr++) {
            const int r = rowBase + wm * 64 + mi * 16 + (lane >> 2) + rr * 8;
            const int bb = r >> 10;
            const int n = r & (SEQ - 1);
            const int nw = half ? ((n & ~31) | permg(n & 31)) : n;
            const float2* rp = g_rope + n * 32 + (d0 >> 1);
            __nv_bfloat16* drow =
                dstBase + ((size_t)(bb * HEADS + h) * SEQ + nw) * HEAD_SIZE;
            uint32_t pk[4];
#pragma unroll
            for (int j = 0; j < 4; j++) {
                const float2 cs2 = __ldg(rp + j);
                const float v0 = acc[mi][j][rr * 2 + 0] * 0.015625f + s_bias[bc + 2 * j];
                const float v1 = acc[mi][j][rr * 2 + 1] * 0.015625f + s_bias[bc + 2 * j + 1];
                __nv_bfloat162 o;
                o.x = __float2bfloat16(v0 * cs2.x - v1 * cs2.y);
                o.y = __float2bfloat16(v1 * cs2.x + v0 * cs2.y);
                pk[j] = *(uint32_t*)&o;
            }
            uint4 u;
            u.x = pk[0]; u.y = pk[1]; u.z = pk[2]; u.w = pk[3];
            *(uint4*)(drow + d0) = u;
        }
    }
}

// ---------------------------------------------------------------------------
// Kernel 2: logits tile 128(m) x 64(n) per CTA, 3 CTAs/SM (unchanged R12/13).
// ---------------------------------------------------------------------------
__global__ void __launch_bounds__(256, 3) logits_kernel(const float* __restrict__ mask,
                                                        float* __restrict__ out) {
    __shared__ __align__(128) __nv_bfloat16 sQ[128 * 64];  // 16KB
    __shared__ __align__(128) __nv_bfloat16 sK[64 * 64];   // 8KB
    __shared__ float s_mk[64];

    const int tid = threadIdx.x;
    const int lane = tid & 31;
    const int wid = tid >> 5;
    const int wm = wid & 3;    // 0..3 (m)
    const int wn = wid >> 2;   // 0..1 (n)
    const int z = blockIdx.z;
    const int b = z / HEADS;
    const int m0 = blockIdx.y << 7;
    const int n0 = blockIdx.x << 6;

    if (tid < 64) s_mk[tid] = mask[(size_t)b * SEQ + n0 + tid];

    float acc[2][4][4] = {};

    const bool skip = (m0 >= n0 + 64);   // tile strictly below diagonal
    if (!skip) {
        const __nv_bfloat16* qsrc = g_q + ((size_t)z * SEQ + m0) * HEAD_SIZE;
        const __nv_bfloat16* ksrc = g_k + ((size_t)z * SEQ + n0) * HEAD_SIZE;

#pragma unroll
        for (int i = 0; i < 4; i++) {     // 1024 uint4 for Q
            int e = tid + i * 256;
            uint32_t so = SWZ((uint32_t)(e * 16));
            *(uint4*)((char*)sQ + so) = ((const uint4*)qsrc)[e];
        }
#pragma unroll
        for (int i = 0; i < 2; i++) {     // 512 uint4 for K
            int e = tid + i * 256;
            uint32_t so = SWZ((uint32_t)(e * 16));
            *(uint4*)((char*)sK + so) = ((const uint4*)ksrc)[e];
        }
        __syncthreads();

        const uint32_t sQb = smem_u32(sQ);
        const uint32_t sKb = smem_u32(sK);

#pragma unroll
        for (int ks = 0; ks < 4; ks++) {
            uint32_t aF[2][4], bF[4][2];
#pragma unroll
            for (int mi = 0; mi < 2; mi++) {
                int r = wm * 32 + mi * 16 + (lane & 15);
                int cc = ks * 2 + (lane >> 4);
                ldmx4(aF[mi], sQb + SWZ((uint32_t)(r * 128 + cc * 16)));
            }
#pragma unroll
            for (int ni = 0; ni < 4; ni++) {
                int l = lane & 15;
                int r = wn * 32 + ni * 8 + (l & 7);
                int cc = ks * 2 + (l >> 3);
                ldmx2(bF[ni], sKb + SWZ((uint32_t)(r * 128 + cc * 16)));
            }
#pragma unroll
            for (int mi = 0; mi < 2; mi++)
#pragma unroll
                for (int ni = 0; ni < 4; ni++)
                    mma16816(acc[mi][ni], aF[mi], bF[ni]);
        }
    } else {
        __syncthreads();
    }

    // Epilogue: lane owns cols bc..bc+7; folded mask/causal/scale; STG.256.cs.
    const int bc = wn * 32 + (lane & 3) * 8;
    float s_j[8], o_j[8];
#pragma unroll
    for (int j = 0; j < 8; j++) {
        const float mk = s_mk[bc + j];
        s_j[j] = mk * 0.125f;
        o_j[j] = (NEGV * 0.125f) * (mk - 1.0f);
    }
#pragma unroll
    for (int mi = 0; mi < 2; mi++) {
#pragma unroll
        for (int rr = 0; rr < 2; rr++) {
            const int m = m0 + wm * 32 + mi * 16 + (lane >> 2) + rr * 8;
            const float mq = mask[(size_t)b * SEQ + m];
            const float rbias = NEGV * (mq - 1.0f);
            float* orow = out + ((size_t)z * SEQ + m) * SEQ + n0;
            float v[8];
#pragma unroll
            for (int j = 0; j < 4; j++) {
#pragma unroll
                for (int q = 0; q < 2; q++) {
                    const int jj = 2 * j + q;
                    const float t = fmaf(acc[mi][j][rr * 2 + q], mq, rbias);
                    float r = fmaf(t, s_j[jj], o_j[jj]);
                    if (m > n0 + bc + jj) r -= (NEGV * 0.125f);
                    v[jj] = r;
                }
            }
            stg256_cs(orow + bc, v);
        }
    }
}

// ---------------------------------------------------------------------------
extern "C" void kernel_launch(void* const* d_in, const int* in_sizes, int n_in,
                              void* d_out, int out_size) {
    const float* x = (const float*)d_in[0];
    const float* W = (const float*)d_in[1];
    const float* bias = (const float*)d_in[2];
    const float* mask = (const float*)d_in[3];
    float* out = (float*)d_out;

    cudaFuncSetAttribute(proj_kernel,
                         cudaFuncAttributeMaxDynamicSharedMemorySize, PROJ_SMEM);

    rope_table_kernel<<<(SEQ * 32) / 256, 256>>>();
    conv_x_kernel<<<(NB * SEQ * HIDDEN / 8) / 256, 256>>>(x);
    conv_wt_kernel<<<dim3(EPROJ / 32, HIDDEN / 32), dim3(32, 8)>>>(W);

    proj_kernel<<<dim3(EPROJ / 128, NB * SEQ / 128), 256, PROJ_SMEM>>>(bias);

    logits_kernel<<<dim3(SEQ / 64, SEQ / 128, NB * HEADS), 256>>>(mask, out);
}

// round 16
// speedup vs baseline: 1.0858x; 1.0355x over previous
#include <cuda_runtime.h>
#include <cuda_bf16.h>
#include <stdint.h>
#include <math.h>

#define HEADS 12
#define HEAD_SIZE 64
#define HIDDEN 768
#define EPROJ 1536
#define SEQ 1024
#define NB 8
#define NEGV 1000000000000.0f

// staging buffers
__device__ __align__(128) uint8_t g_x8[NB * SEQ * HIDDEN];          // x e4m3, scale 1
__device__ __align__(128) uint8_t g_w8[EPROJ * HIDDEN];             // W^T e4m3 *64, rows permuted
__device__ __align__(128) __nv_bfloat16 g_q[NB * HEADS * SEQ * HEAD_SIZE];
__device__ __align__(128) __nv_bfloat16 g_k[NB * HEADS * SEQ * HEAD_SIZE]; // rows permuted
__device__ __align__(128) float2 g_rope[SEQ * 32];                  // [n][freq] = (cos, sin)

#define SWZ(o) ((o) ^ (((o) >> 3) & 0x70))     // 128B rows
#define SWZ64(o) ((o) ^ (((o) >> 3) & 0x30))   // 64B rows

// Involutive permutation within 32-row groups.
__device__ __forceinline__ int permg(int c) {
    return (((c & 7) >> 1) << 3) + ((c >> 3) << 1) + (c & 1);
}

__device__ __forceinline__ uint32_t smem_u32(const void* p) {
    uint32_t a;
    asm("{ .reg .u64 t; cvta.to.shared.u64 t, %1; cvt.u32.u64 %0, t; }"
        : "=r"(a) : "l"(p));
    return a;
}

__device__ __forceinline__ void ldmx4(uint32_t* r, uint32_t addr) {
    asm volatile("ldmatrix.sync.aligned.m8n8.x4.shared.b16 {%0,%1,%2,%3}, [%4];"
                 : "=r"(r[0]), "=r"(r[1]), "=r"(r[2]), "=r"(r[3]) : "r"(addr));
}
__device__ __forceinline__ void ldmx2(uint32_t* r, uint32_t addr) {
    asm volatile("ldmatrix.sync.aligned.m8n8.x2.shared.b16 {%0,%1}, [%2];"
                 : "=r"(r[0]), "=r"(r[1]) : "r"(addr));
}
__device__ __forceinline__ void mma16816(float* c, const uint32_t* a,
                                         const uint32_t* b) {
    asm volatile(
        "mma.sync.aligned.m16n8k16.row.col.f32.bf16.bf16.f32 "
        "{%0,%1,%2,%3}, {%4,%5,%6,%7}, {%8,%9}, {%0,%1,%2,%3};"
        : "+f"(c[0]), "+f"(c[1]), "+f"(c[2]), "+f"(c[3])
        : "r"(a[0]), "r"(a[1]), "r"(a[2]), "r"(a[3]), "r"(b[0]), "r"(b[1]));
}
// fp8 e4m3 mma, K=32, fp32 accum
__device__ __forceinline__ void mma8(float* c, const uint32_t* a,
                                     const uint32_t* b) {
    asm volatile(
        "mma.sync.aligned.m16n8k32.row.col.f32.e4m3.e4m3.f32 "
        "{%0,%1,%2,%3}, {%4,%5,%6,%7}, {%8,%9}, {%0,%1,%2,%3};"
        : "+f"(c[0]), "+f"(c[1]), "+f"(c[2]), "+f"(c[3])
        : "r"(a[0]), "r"(a[1]), "r"(a[2]), "r"(a[3]), "r"(b[0]), "r"(b[1]));
}

__device__ __forceinline__ uint16_t pack2_e4m3(float lo, float hi) {
    uint16_t r;
    asm("cvt.rn.satfinite.e4m3x2.f32 %0, %1, %2;" : "=h"(r) : "f"(hi), "f"(lo));
    return r;
}
__device__ __forceinline__ uint32_t pack4_e4m3(float a0, float a1, float a2,
                                               float a3) {
    uint16_t lo = pack2_e4m3(a0, a1);
    uint16_t hi = pack2_e4m3(a2, a3);
    return (uint32_t)lo | ((uint32_t)hi << 16);
}

// 256-bit streaming store (Blackwell): 32 lanes x 32B = 8 full 128B lines.
__device__ __forceinline__ void stg256_cs(float* p, const float* v) {
    asm volatile(
        "st.global.cs.v8.f32 [%0], {%1,%2,%3,%4,%5,%6,%7,%8};"
        :: "l"(p), "f"(v[0]), "f"(v[1]), "f"(v[2]), "f"(v[3]),
           "f"(v[4]), "f"(v[5]), "f"(v[6]), "f"(v[7])
        : "memory");
}

#define CP_ASYNC16(dst, src) \
    asm volatile("cp.async.cg.shared.global [%0], [%1], 16;" \
                 :: "r"(dst), "l"(src) : "memory")
#define CP_COMMIT asm volatile("cp.async.commit_group;" ::: "memory")
#define CP_WAIT0 asm volatile("cp.async.wait_group 0;" ::: "memory")
#define CP_WAIT1 asm volatile("cp.async.wait_group 1;" ::: "memory")

// ---------------------------------------------------------------------------
// conversion / table kernels
// ---------------------------------------------------------------------------
__global__ void rope_table_kernel() {
    const int i = blockIdx.x * blockDim.x + threadIdx.x;  // n*32 + freq
    const int n = i >> 5;
    const int f = i & 31;
    const float inv = exp2f(-(float)(2 * f) * (13.287712379549449f / 64.0f));
    float s, c;
    sincosf((float)n * inv, &s, &c);
    g_rope[i] = make_float2(c, s);
}

__global__ void conv_x_kernel(const float* __restrict__ x) {
    int i = blockIdx.x * blockDim.x + threadIdx.x;  // 8 floats per thread
    float4 v0 = ((const float4*)x)[i * 2];
    float4 v1 = ((const float4*)x)[i * 2 + 1];
    uint2 u;
    u.x = pack4_e4m3(v0.x, v0.y, v0.z, v0.w);
    u.y = pack4_e4m3(v1.x, v1.y, v1.z, v1.w);
    ((uint2*)g_x8)[i] = u;
}

// W^T e4m3 (*64), rows permuted within aligned 32-groups.
__global__ void conv_wt_kernel(const float* __restrict__ W) {
    __shared__ float t[32][33];
    const int bx = blockIdx.x * 32, by = blockIdx.y * 32;
    const int tx = threadIdx.x, ty = threadIdx.y;
#pragma unroll
    for (int j = 0; j < 4; j++)
        t[ty + j * 8][tx] = W[(size_t)(by + ty + j * 8) * EPROJ + bx + tx];
    __syncthreads();
    const int r2 = ty + (tx >> 3) * 8;
    const int c4 = (tx & 7) * 4;
    uint32_t p = pack4_e4m3(t[c4 + 0][r2] * 64.f, t[c4 + 1][r2] * 64.f,
                            t[c4 + 2][r2] * 64.f, t[c4 + 3][r2] * 64.f);
    *(uint32_t*)(g_w8 + (size_t)(bx + permg(r2)) * HIDDEN + by + c4) = p;
}

// ---------------------------------------------------------------------------
// Kernel 1: proj = x @ W (+bias) then RoPE -> g_q / g_k (bf16)
// FP8 e4m3 mma, CTA tile 128x128, K in 12 chunks of 64, cp.async 3-stage
// pipeline with wait_group 1 (each stage has ~2 mma phases of load slack).
// Stage: A 8KB + B 8KB (64B rows, SW64). Stages at s*16384; bias at 49152.
// ---------------------------------------------------------------------------
#define PROJ_SMEM (49152 + 512)

__global__ void __launch_bounds__(256, 2) proj_kernel(const float* __restrict__ bias) {
    extern __shared__ __align__(128) uint8_t dsm[];
    float* s_bias = (float*)(dsm + 49152);

    const int tid = threadIdx.x;
    const int lane = tid & 31;
    const int wid = tid >> 5;
    const int wm = wid & 1;
    const int wn = wid >> 1;
    const int h = blockIdx.x;
    const int rowBase = blockIdx.y * 128;
    const int colBase = h * 128;

    if (tid < 128) s_bias[tid] = bias[colBase + tid];

    const uint32_t sbase = smem_u32(dsm);

    // Per-thread load slots: 2 uint4 per 8KB tile (512 uint4, 256 threads).
    int lr[2], lc[2];
    uint32_t lso[2];
#pragma unroll
    for (int i = 0; i < 2; i++) {
        int e = tid + i * 256;
        lr[i] = e >> 2;              // row 0..127 (4 uint4 per 64B row)
        lc[i] = (e & 3) * 16;
        lso[i] = SWZ64((uint32_t)(lr[i] * 64 + (e & 3) * 16));
    }

#define PROJ_ISSUE(ch)                                                        \
    {                                                                         \
        const int k0_ = (ch) * 64;                                            \
        const uint32_t sb_ = sbase + ((ch) % 3) * 16384;                      \
        _Pragma("unroll") for (int i = 0; i < 2; i++) {                       \
            CP_ASYNC16(sb_ + lso[i],                                          \
                       g_x8 + (size_t)(rowBase + lr[i]) * HIDDEN + k0_ + lc[i]); \
            CP_ASYNC16(sb_ + 8192 + lso[i],                                   \
                       g_w8 + (size_t)(colBase + lr[i]) * HIDDEN + k0_ + lc[i]); \
        }                                                                     \
        CP_COMMIT;                                                            \
    }

    float acc[4][4][4] = {};

    PROJ_ISSUE(0);
    PROJ_ISSUE(1);
    for (int ch = 0; ch < 12; ch++) {
        if (ch < 11) { CP_WAIT1; }   // stage ch done; stage ch+1 may be in flight
        else { CP_WAIT0; }
        __syncthreads();             // all warps past mma(ch-1) -> stage (ch+2)%3 free
        if (ch < 10) PROJ_ISSUE(ch + 2);

        const uint32_t sAb = sbase + (ch % 3) * 16384;
        const uint32_t sBb = sAb + 8192;
#pragma unroll
        for (int ks = 0; ks < 2; ks++) {   // 2 x K=32 per 64B chunk
            uint32_t aF[4][4], bF[4][2];
#pragma unroll
            for (int mi = 0; mi < 4; mi++) {
                int r = wm * 64 + mi * 16 + (lane & 15);
                int cc = ks * 2 + (lane >> 4);
                ldmx4(aF[mi], sAb + SWZ64((uint32_t)(r * 64 + cc * 16)));
            }
            // B: one ldmx4 per ni-pair (4 tiles: ni0/kc0, ni0/kc1, ni1/kc0, ni1/kc1)
#pragma unroll
            for (int p = 0; p < 2; p++) {
                const int ni = p * 2 + (lane >> 4);          // address lanes
                const int kc = (lane >> 3) & 1;
                const int r = wn * 32 + ni * 8 + (lane & 7);
                const int cc = ks * 2 + kc;
                uint32_t t4[4];
                ldmx4(t4, sBb + SWZ64((uint32_t)(r * 64 + cc * 16)));
                bF[p * 2 + 0][0] = t4[0]; bF[p * 2 + 0][1] = t4[1];
                bF[p * 2 + 1][0] = t4[2]; bF[p * 2 + 1][1] = t4[3];
            }
#pragma unroll
            for (int mi = 0; mi < 4; mi++)
#pragma unroll
                for (int ni = 0; ni < 4; ni++)
                    mma8(acc[mi][ni], aF[mi], bF[ni]);
        }
    }

    // Epilogue: lane owns cols bc..bc+7; unscale 1/64, +bias, RoPE (table),
    // bf16, one 16B store per (mi, rr). k rows stored permuted.
    const int bc = wn * 32 + (lane & 3) * 8;
    const int half = (bc >> 6) & 1;
    const int d0 = bc & 63;
    __nv_bfloat16* dstBase = half ? g_k : g_q;
#pragma unroll
    for (int mi = 0; mi < 4; mi++) {
#pragma unroll
        for (int rr = 0; rr < 2; rr++) {
            const int r = rowBase + wm * 64 + mi * 16 + (lane >> 2) + rr * 8;
            const int bb = r >> 10;
            const int n = r & (SEQ - 1);
            const int nw = half ? ((n & ~31) | permg(n & 31)) : n;
            const float2* rp = g_rope + n * 32 + (d0 >> 1);
            __nv_bfloat16* drow =
                dstBase + ((size_t)(bb * HEADS + h) * SEQ + nw) * HEAD_SIZE;
            uint32_t pk[4];
#pragma unroll
            for (int j = 0; j < 4; j++) {
                const float2 cs2 = __ldg(rp + j);
                const float v0 = acc[mi][j][rr * 2 + 0] * 0.015625f + s_bias[bc + 2 * j];
                const float v1 = acc[mi][j][rr * 2 + 1] * 0.015625f + s_bias[bc + 2 * j + 1];
                __nv_bfloat162 o;
                o.x = __float2bfloat16(v0 * cs2.x - v1 * cs2.y);
                o.y = __float2bfloat16(v1 * cs2.x + v0 * cs2.y);
                pk[j] = *(uint32_t*)&o;
            }
            uint4 u;
            u.x = pk[0]; u.y = pk[1]; u.z = pk[2]; u.w = pk[3];
            *(uint4*)(drow + d0) = u;
        }
    }
}

// ---------------------------------------------------------------------------
// Kernel 2: logits tile 128(m) x 64(n) per CTA, 3 CTAs/SM (unchanged R12-15).
// ---------------------------------------------------------------------------
__global__ void __launch_bounds__(256, 3) logits_kernel(const float* __restrict__ mask,
                                                        float* __restrict__ out) {
    __shared__ __align__(128) __nv_bfloat16 sQ[128 * 64];  // 16KB
    __shared__ __align__(128) __nv_bfloat16 sK[64 * 64];   // 8KB
    __shared__ float s_mk[64];

    const int tid = threadIdx.x;
    const int lane = tid & 31;
    const int wid = tid >> 5;
    const int wm = wid & 3;    // 0..3 (m)
    const int wn = wid >> 2;   // 0..1 (n)
    const int z = blockIdx.z;
    const int b = z / HEADS;
    const int m0 = blockIdx.y << 7;
    const int n0 = blockIdx.x << 6;

    if (tid < 64) s_mk[tid] = mask[(size_t)b * SEQ + n0 + tid];

    float acc[2][4][4] = {};

    const bool skip = (m0 >= n0 + 64);   // tile strictly below diagonal
    if (!skip) {
        const __nv_bfloat16* qsrc = g_q + ((size_t)z * SEQ + m0) * HEAD_SIZE;
        const __nv_bfloat16* ksrc = g_k + ((size_t)z * SEQ + n0) * HEAD_SIZE;

#pragma unroll
        for (int i = 0; i < 4; i++) {     // 1024 uint4 for Q
            int e = tid + i * 256;
            uint32_t so = SWZ((uint32_t)(e * 16));
            *(uint4*)((char*)sQ + so) = ((const uint4*)qsrc)[e];
        }
#pragma unroll
        for (int i = 0; i < 2; i++) {     // 512 uint4 for K
            int e = tid + i * 256;
            uint32_t so = SWZ((uint32_t)(e * 16));
            *(uint4*)((char*)sK + so) = ((const uint4*)ksrc)[e];
        }
        __syncthreads();

        const uint32_t sQb = smem_u32(sQ);
        const uint32_t sKb = smem_u32(sK);

#pragma unroll
        for (int ks = 0; ks < 4; ks++) {
            uint32_t aF[2][4], bF[4][2];
#pragma unroll
            for (int mi = 0; mi < 2; mi++) {
                int r = wm * 32 + mi * 16 + (lane & 15);
                int cc = ks * 2 + (lane >> 4);
                ldmx4(aF[mi], sQb + SWZ((uint32_t)(r * 128 + cc * 16)));
            }
#pragma unroll
            for (int ni = 0; ni < 4; ni++) {
                int l = lane & 15;
                int r = wn * 32 + ni * 8 + (l & 7);
                int cc = ks * 2 + (l >> 3);
                ldmx2(bF[ni], sKb + SWZ((uint32_t)(r * 128 + cc * 16)));
            }
#pragma unroll
            for (int mi = 0; mi < 2; mi++)
#pragma unroll
                for (int ni = 0; ni < 4; ni++)
                    mma16816(acc[mi][ni], aF[mi], bF[ni]);
        }
    } else {
        __syncthreads();
    }

    // Epilogue: lane owns cols bc..bc+7; folded mask/causal/scale; STG.256.cs.
    const int bc = wn * 32 + (lane & 3) * 8;
    float s_j[8], o_j[8];
#pragma unroll
    for (int j = 0; j < 8; j++) {
        const float mk = s_mk[bc + j];
        s_j[j] = mk * 0.125f;
        o_j[j] = (NEGV * 0.125f) * (mk - 1.0f);
    }
#pragma unroll
    for (int mi = 0; mi < 2; mi++) {
#pragma unroll
        for (int rr = 0; rr < 2; rr++) {
            const int m = m0 + wm * 32 + mi * 16 + (lane >> 2) + rr * 8;
            const float mq = mask[(size_t)b * SEQ + m];
            const float rbias = NEGV * (mq - 1.0f);
            float* orow = out + ((size_t)z * SEQ + m) * SEQ + n0;
            float v[8];
#pragma unroll
            for (int j = 0; j < 4; j++) {
#pragma unroll
                for (int q = 0; q < 2; q++) {
                    const int jj = 2 * j + q;
                    const float t = fmaf(acc[mi][j][rr * 2 + q], mq, rbias);
                    float r = fmaf(t, s_j[jj], o_j[jj]);
                    if (m > n0 + bc + jj) r -= (NEGV * 0.125f);
                    v[jj] = r;
                }
            }
            stg256_cs(orow + bc, v);
        }
    }
}

// ---------------------------------------------------------------------------
extern "C" void kernel_launch(void* const* d_in, const int* in_sizes, int n_in,
                              void* d_out, int out_size) {
    const float* x = (const float*)d_in[0];
    const float* W = (const float*)d_in[1];
    const float* bias = (const float*)d_in[2];
    const float* mask = (const float*)d_in[3];
    float* out = (float*)d_out;

    cudaFuncSetAttribute(proj_kernel,
                         cudaFuncAttributeMaxDynamicSharedMemorySize, PROJ_SMEM);

    rope_table_kernel<<<(SEQ * 32) / 256, 256>>>();
    conv_x_kernel<<<(NB * SEQ * HIDDEN / 8) / 256, 256>>>(x);
    conv_wt_kernel<<<dim3(EPROJ / 32, HIDDEN / 32), dim3(32, 8)>>>(W);

    proj_kernel<<<dim3(EPROJ / 128, NB * SEQ / 128), 256, PROJ_SMEM>>>(bias);

    logits_kernel<<<dim3(SEQ / 64, SEQ / 128, NB * HEADS), 256>>>(mask, out);
}